// round 1
// baseline (speedup 1.0000x reference)
#include <cuda_runtime.h>
#include <math.h>

// Problem constants (from reference): N_NODES=8192, dims 512->256->128, 2 views.
#define NND 8192
#define D1  512
#define D2  256
#define D3  128

// Scratch (device globals; no allocation allowed)
__device__ float g_s1[NND * D2];   // x @ W1
__device__ float g_h [NND * D2];   // spmm1 accumulator
__device__ float g_s2[NND * D3];   // relu(h) @ W2
__device__ float g_za[NND * D3];   // spmm2 accumulator

// ---------------------------------------------------------------------------
// zero fill
__global__ void kzero(float* p, int n) {
    int i = blockIdx.x * blockDim.x + threadIdx.x;
    int stride = gridDim.x * blockDim.x;
    for (; i < n; i += stride) p[i] = 0.0f;
}

// ---------------------------------------------------------------------------
// Generic tiled fp32 GEMM: C[M,N] = act(A)[M,K] @ B[K,N], all row-major.
// 64x64 block tile, 16x16 threads, 4x4 microtile, K-chunk 32.
// Requires M%64==0, N%64==0, K%32==0 (true for all shapes here).
template<bool RELU_A>
__global__ void gemm64(const float* __restrict__ A, const float* __restrict__ B,
                       float* __restrict__ C, int M, int N, int K) {
    __shared__ float As[32 * 65];
    __shared__ float Bs[32 * 65];
    const int tid = threadIdx.x;
    const int tx = tid & 15, ty = tid >> 4;
    const int r0 = blockIdx.y * 64, c0 = blockIdx.x * 64;

    float acc[4][4];
#pragma unroll
    for (int i = 0; i < 4; i++)
#pragma unroll
        for (int j = 0; j < 4; j++) acc[i][j] = 0.0f;

    for (int kc = 0; kc < K; kc += 32) {
        // Load A tile (64 rows x 32 k), transposed into As[k][row]
#pragma unroll
        for (int i = 0; i < 8; i++) {
            int idx = tid + i * 256;
            int row = idx >> 5, k = idx & 31;
            float v = A[(size_t)(r0 + row) * K + kc + k];
            if (RELU_A) v = fmaxf(v, 0.0f);
            As[k * 65 + row] = v;
        }
        // Load B tile (32 k x 64 cols) into Bs[k][col]
#pragma unroll
        for (int i = 0; i < 8; i++) {
            int idx = tid + i * 256;
            int k = idx >> 6, col = idx & 63;
            Bs[k * 65 + col] = B[(size_t)(kc + k) * N + c0 + col];
        }
        __syncthreads();

#pragma unroll
        for (int k = 0; k < 32; k++) {
            float a[4], b[4];
#pragma unroll
            for (int i = 0; i < 4; i++) a[i] = As[k * 65 + ty * 4 + i];
#pragma unroll
            for (int j = 0; j < 4; j++) b[j] = Bs[k * 65 + tx * 4 + j];
#pragma unroll
            for (int i = 0; i < 4; i++)
#pragma unroll
                for (int j = 0; j < 4; j++) acc[i][j] += a[i] * b[j];
        }
        __syncthreads();
    }

#pragma unroll
    for (int i = 0; i < 4; i++) {
        float4 v = make_float4(acc[i][0], acc[i][1], acc[i][2], acc[i][3]);
        *(float4*)(C + (size_t)(r0 + ty * 4 + i) * N + c0 + tx * 4) = v;
    }
}

// ---------------------------------------------------------------------------
// Edge-parallel SpMM with atomics: out[rows[e]] += vals[e] * h[cols[e]]
// One warp per edge; float4 gathers; scalar fp32 atomicAdd (RED) to L2.
__global__ void spmm_atom(const float* __restrict__ h, const float* __restrict__ vals,
                          const int* __restrict__ rows, const int* __restrict__ cols,
                          float* __restrict__ out, int nE, int F) {
    int w = (blockIdx.x * blockDim.x + threadIdx.x) >> 5;
    if (w >= nE) return;
    int lane = threadIdx.x & 31;
    float v = vals[w];
    size_t c = (size_t)cols[w];
    size_t r = (size_t)rows[w];
    const float4* hp = (const float4*)(h + c * F);
    float* op = out + r * F;
    int nq = F >> 2;  // float4 count: 64 (F=256) or 32 (F=128)
    for (int f = lane; f < nq; f += 32) {
        float4 t = hp[f];
        atomicAdd(op + f * 4 + 0, v * t.x);
        atomicAdd(op + f * 4 + 1, v * t.y);
        atomicAdd(op + f * 4 + 2, v * t.z);
        atomicAdd(op + f * 4 + 3, v * t.w);
    }
}

// ---------------------------------------------------------------------------
// z = relu(zacc), written to output
__global__ void relu_copy(const float* __restrict__ in, float* __restrict__ out, int n) {
    int i = blockIdx.x * blockDim.x + threadIdx.x;
    if (i < n) out[i] = fmaxf(in[i], 0.0f);
}

// ---------------------------------------------------------------------------
// rec = Z @ Z^T (symmetric), written to both views.
// Upper-triangle blocks (by <= bx) compute; mirror tile written via smem
// transpose staging (reusing the operand-panel smem).
__global__ void zzsym(const float* __restrict__ Z, float* __restrict__ rec) {
    const int bx = blockIdx.x, by = blockIdx.y;
    if (by > bx) return;

    __shared__ float sm[64 * 65];      // = 2 * (32*65): As + Bs; reused as transpose tile
    float* As = sm;
    float* Bs = sm + 32 * 65;

    const int tid = threadIdx.x;
    const int tx = tid & 15, ty = tid >> 4;
    const int r0 = by * 64, c0 = bx * 64;

    float acc[4][4];
#pragma unroll
    for (int i = 0; i < 4; i++)
#pragma unroll
        for (int j = 0; j < 4; j++) acc[i][j] = 0.0f;

    for (int kc = 0; kc < D3; kc += 32) {
#pragma unroll
        for (int i = 0; i < 8; i++) {
            int idx = tid + i * 256;
            int row = idx >> 5, k = idx & 31;
            As[k * 65 + row] = Z[(size_t)(r0 + row) * D3 + kc + k];
            Bs[k * 65 + row] = Z[(size_t)(c0 + row) * D3 + kc + k];
        }
        __syncthreads();
#pragma unroll
        for (int k = 0; k < 32; k++) {
            float a[4], b[4];
#pragma unroll
            for (int i = 0; i < 4; i++) a[i] = As[k * 65 + ty * 4 + i];
#pragma unroll
            for (int j = 0; j < 4; j++) b[j] = Bs[k * 65 + tx * 4 + j];
#pragma unroll
            for (int i = 0; i < 4; i++)
#pragma unroll
                for (int j = 0; j < 4; j++) acc[i][j] += a[i] * b[j];
        }
        __syncthreads();
    }

    const size_t NN = (size_t)NND * NND;

    // Direct tile to both views
#pragma unroll
    for (int i = 0; i < 4; i++) {
        float4 v = make_float4(acc[i][0], acc[i][1], acc[i][2], acc[i][3]);
        size_t off = (size_t)(r0 + ty * 4 + i) * NND + c0 + tx * 4;
        *(float4*)(rec + off) = v;
        *(float4*)(rec + NN + off) = v;
    }

    if (bx != by) {
        // Stage tile into smem for coalesced transposed writes
#pragma unroll
        for (int i = 0; i < 4; i++)
#pragma unroll
            for (int j = 0; j < 4; j++)
                sm[(ty * 4 + i) * 65 + tx * 4 + j] = acc[i][j];
        __syncthreads();
#pragma unroll
        for (int i = 0; i < 4; i++) {
            float4 v;
            v.x = sm[(tx * 4 + 0) * 65 + ty * 4 + i];
            v.y = sm[(tx * 4 + 1) * 65 + ty * 4 + i];
            v.z = sm[(tx * 4 + 2) * 65 + ty * 4 + i];
            v.w = sm[(tx * 4 + 3) * 65 + ty * 4 + i];
            size_t off = (size_t)(c0 + ty * 4 + i) * NND + r0 + tx * 4;
            *(float4*)(rec + off) = v;
            *(float4*)(rec + NN + off) = v;
        }
    }
}

// ---------------------------------------------------------------------------
extern "C" void kernel_launch(void* const* d_in, const int* in_sizes, int n_in,
                              void* d_out, int out_size) {
    const float* x  = (const float*)d_in[0];
    const float* W1 = (const float*)d_in[1];
    const float* W2 = (const float*)d_in[2];
    const float* ev = (const float*)d_in[3];
    const int*   er = (const int*)d_in[4];
    const int*   ec = (const int*)d_in[5];
    const int nE = in_sizes[3];

    float* out   = (float*)d_out;
    float* z_out = out;                        // [NND, D3]
    float* rec   = out + (size_t)NND * D3;     // [2, NND, NND]

    float *p_s1, *p_h, *p_s2, *p_za;
    cudaGetSymbolAddress((void**)&p_s1, g_s1);
    cudaGetSymbolAddress((void**)&p_h,  g_h);
    cudaGetSymbolAddress((void**)&p_s2, g_s2);
    cudaGetSymbolAddress((void**)&p_za, g_za);

    // Zero SpMM accumulators
    kzero<<<1024, 256>>>(p_h,  NND * D2);
    kzero<<<1024, 256>>>(p_za, NND * D3);

    // Layer 1: support = x @ W1
    gemm64<false><<<dim3(D2 / 64, NND / 64), 256>>>(x, W1, p_s1, NND, D2, D1);
    // h = spmm(support)  (relu deferred to GEMM2 load)
    spmm_atom<<<(nE + 7) / 8, 256>>>(p_s1, ev, er, ec, p_h, nE, D2);

    // Layer 2: support2 = relu(h) @ W2
    gemm64<true><<<dim3(D3 / 64, NND / 64), 256>>>(p_h, W2, p_s2, NND, D3, D2);
    // zacc = spmm(support2)
    spmm_atom<<<(nE + 7) / 8, 256>>>(p_s2, ev, er, ec, p_za, nE, D3);

    // z = relu(zacc) -> output
    relu_copy<<<(NND * D3 + 255) / 256, 256>>>(p_za, z_out, NND * D3);

    // rec_views = stack([z @ z.T] * 2)
    zzsym<<<dim3(NND / 64, NND / 64), 256>>>(z_out, rec);
}

// round 2
// speedup vs baseline: 1.3340x; 1.3340x over previous
#include <cuda_runtime.h>
#include <math.h>

#define NND 8192
#define D1  512
#define D2  256
#define D3  128
#define NEDGE 262144

typedef unsigned long long u64;

// Scratch (device globals)
__device__ float g_s1[NND * D2];     // x @ W1
__device__ float g_h [NND * D2];     // relu(spmm1)
__device__ float g_s2[NND * D3];     // h @ W2
__device__ int   g_cnt[NND];
__device__ int   g_off[NND + 1];
__device__ int   g_cur[NND];
__device__ int   g_ecol[NEDGE];
__device__ float g_eval[NEDGE];

__device__ __forceinline__ void ffma2(u64& d, u64 a, u64 b) {
    asm("fma.rn.f32x2 %0, %1, %2, %3;" : "=l"(d) : "l"(a), "l"(b), "l"(d));
}
__device__ __forceinline__ u64 dup2(float x) {
    u64 r;
    asm("mov.b64 %0, {%1, %1};" : "=l"(r) : "r"(__float_as_uint(x)));
    return r;
}

// ---------------------------------------------------------------------------
__global__ void kzero_i(int* p, int n) {
    int i = blockIdx.x * blockDim.x + threadIdx.x;
    if (i < n) p[i] = 0;
}
__global__ void count_edges(const int* __restrict__ er, int* __restrict__ cnt, int nE) {
    int e = blockIdx.x * blockDim.x + threadIdx.x;
    if (e < nE) atomicAdd(&cnt[er[e]], 1);
}
// Exclusive scan of 8192 counts, one block of 1024 threads (8 each).
__global__ void scan8192(const int* __restrict__ cnt, int* __restrict__ off) {
    __shared__ int s[1024];
    int t = threadIdx.x;
    int base = t * 8;
    int loc[8];
    int sum = 0;
#pragma unroll
    for (int i = 0; i < 8; i++) { loc[i] = sum; sum += cnt[base + i]; }
    s[t] = sum;
    __syncthreads();
    for (int d = 1; d < 1024; d <<= 1) {
        int v = 0;
        if (t >= d) v = s[t - d];
        __syncthreads();
        if (t >= d) s[t] += v;
        __syncthreads();
    }
    int pre = (t == 0) ? 0 : s[t - 1];
#pragma unroll
    for (int i = 0; i < 8; i++) off[base + i] = pre + loc[i];
    if (t == 1023) off[NND] = s[1023];
}
__global__ void copy_off(const int* __restrict__ off, int* __restrict__ cur, int n) {
    int i = blockIdx.x * blockDim.x + threadIdx.x;
    if (i < n) cur[i] = off[i];
}
__global__ void scatter_edges(const int* __restrict__ er, const int* __restrict__ ec,
                              const float* __restrict__ ev, int* __restrict__ cur,
                              int* __restrict__ ecol, float* __restrict__ eval, int nE) {
    int e = blockIdx.x * blockDim.x + threadIdx.x;
    if (e >= nE) return;
    int r = er[e];
    int p = atomicAdd(&cur[r], 1);
    ecol[p] = ec[e];
    eval[p] = ev[e];
}

// ---------------------------------------------------------------------------
// Gather SpMM: out[r] = relu( sum_j val[j] * h[col[j]] ), one block per row,
// one thread per feature. All reads from L2-resident h; no atomics.
template<int F, bool RELU>
__global__ void spmm_gather(const float* __restrict__ h, const int* __restrict__ off,
                            const int* __restrict__ ecol, const float* __restrict__ eval,
                            float* __restrict__ out) {
    int r = blockIdx.x, t = threadIdx.x;
    int s = off[r], e = off[r + 1];
    float acc = 0.0f;
    int j = s;
    for (; j + 4 <= e; j += 4) {
        int   c0 = ecol[j], c1 = ecol[j + 1], c2 = ecol[j + 2], c3 = ecol[j + 3];
        float v0 = eval[j], v1 = eval[j + 1], v2 = eval[j + 2], v3 = eval[j + 3];
        float h0 = h[(size_t)c0 * F + t];
        float h1 = h[(size_t)c1 * F + t];
        float h2 = h[(size_t)c2 * F + t];
        float h3 = h[(size_t)c3 * F + t];
        acc += v0 * h0; acc += v1 * h1; acc += v2 * h2; acc += v3 * h3;
    }
    for (; j < e; j++) acc += eval[j] * h[(size_t)ecol[j] * F + t];
    if (RELU) acc = fmaxf(acc, 0.0f);
    out[(size_t)r * F + t] = acc;
}

// ---------------------------------------------------------------------------
// FFMA2 GEMM: C[M,N] = A[M,K] @ B[K,N]. 128x128 tile, 256 thr, 8x8 micro,
// packed f32x2 over N pairs. M%128==0, N%128==0, K%32==0.
#define APAD 36
#define BPAD 136
__global__ __launch_bounds__(256) void gemm128(const float* __restrict__ A,
                                               const float* __restrict__ B,
                                               float* __restrict__ C,
                                               int M, int N, int K) {
    __shared__ float sm[128 * APAD + 32 * BPAD];
    float* As = sm;               // [m][k], stride APAD
    float* Bs = sm + 128 * APAD;  // [k][n], stride BPAD
    const int tid = threadIdx.x;
    const int tx = tid & 15, ty = tid >> 4;
    const int r0 = blockIdx.y * 128, c0 = blockIdx.x * 128;

    u64 acc[8][4];
#pragma unroll
    for (int i = 0; i < 8; i++)
#pragma unroll
        for (int j = 0; j < 4; j++) acc[i][j] = 0ull;

    for (int kc = 0; kc < K; kc += 32) {
#pragma unroll
        for (int i = 0; i < 16; i++) {
            int idx = tid + i * 256;
            int m = idx >> 5, k = idx & 31;
            As[m * APAD + k] = A[(size_t)(r0 + m) * K + kc + k];
        }
#pragma unroll
        for (int i = 0; i < 16; i++) {
            int idx = tid + i * 256;
            int k = idx >> 7, n = idx & 127;
            Bs[k * BPAD + n] = B[(size_t)(kc + k) * N + c0 + n];
        }
        __syncthreads();
#pragma unroll
        for (int k = 0; k < 32; k++) {
            const u64* bp = (const u64*)(Bs + k * BPAD + tx * 8);
            u64 b0 = bp[0], b1 = bp[1], b2 = bp[2], b3 = bp[3];
#pragma unroll
            for (int i = 0; i < 8; i++) {
                u64 aa = dup2(As[(ty * 8 + i) * APAD + k]);
                ffma2(acc[i][0], aa, b0);
                ffma2(acc[i][1], aa, b1);
                ffma2(acc[i][2], aa, b2);
                ffma2(acc[i][3], aa, b3);
            }
        }
        __syncthreads();
    }
#pragma unroll
    for (int i = 0; i < 8; i++) {
        float* cp = C + (size_t)(r0 + ty * 8 + i) * N + c0 + tx * 8;
        float2 p0 = *(float2*)&acc[i][0], p1 = *(float2*)&acc[i][1];
        float2 p2 = *(float2*)&acc[i][2], p3 = *(float2*)&acc[i][3];
        *(float4*)cp       = make_float4(p0.x, p0.y, p1.x, p1.y);
        *(float4*)(cp + 4) = make_float4(p2.x, p2.y, p3.x, p3.y);
    }
}

// ---------------------------------------------------------------------------
// rec = Z @ Z^T (symmetric) into both views. Triangle blocks compute;
// mirrors written via smem-chunk transpose. Same FFMA2 core, K = 128.
__global__ __launch_bounds__(256) void zzsym(const float* __restrict__ Z,
                                             float* __restrict__ rec) {
    const int bx = blockIdx.x, by = blockIdx.y;
    if (by > bx) return;

    __shared__ float sm[128 * APAD + 32 * BPAD];
    float* As = sm;
    float* Bs = sm + 128 * APAD;
    const int tid = threadIdx.x;
    const int tx = tid & 15, ty = tid >> 4;
    const int r0 = by * 128, c0 = bx * 128;

    u64 acc[8][4];
#pragma unroll
    for (int i = 0; i < 8; i++)
#pragma unroll
        for (int j = 0; j < 4; j++) acc[i][j] = 0ull;

    for (int kc = 0; kc < D3; kc += 32) {
#pragma unroll
        for (int i = 0; i < 16; i++) {
            int idx = tid + i * 256;
            int m = idx >> 5, k = idx & 31;
            As[m * APAD + k] = Z[(size_t)(r0 + m) * D3 + kc + k];
        }
        // Bs[k][n] = Z[c0+n][kc+k]: float4 along k, scalar conflict-free stores
#pragma unroll
        for (int i = 0; i < 4; i++) {
            int idx = tid + i * 256;          // 0..1023
            int n = idx & 127, k4 = idx >> 7; // k4 0..7
            float4 v = *(const float4*)(Z + (size_t)(c0 + n) * D3 + kc + k4 * 4);
            Bs[(k4 * 4 + 0) * BPAD + n] = v.x;
            Bs[(k4 * 4 + 1) * BPAD + n] = v.y;
            Bs[(k4 * 4 + 2) * BPAD + n] = v.z;
            Bs[(k4 * 4 + 3) * BPAD + n] = v.w;
        }
        __syncthreads();
#pragma unroll
        for (int k = 0; k < 32; k++) {
            const u64* bp = (const u64*)(Bs + k * BPAD + tx * 8);
            u64 b0 = bp[0], b1 = bp[1], b2 = bp[2], b3 = bp[3];
#pragma unroll
            for (int i = 0; i < 8; i++) {
                u64 aa = dup2(As[(ty * 8 + i) * APAD + k]);
                ffma2(acc[i][0], aa, b0);
                ffma2(acc[i][1], aa, b1);
                ffma2(acc[i][2], aa, b2);
                ffma2(acc[i][3], aa, b3);
            }
        }
        __syncthreads();
    }

    const size_t NN = (size_t)NND * NND;

    // Direct tile -> both views
#pragma unroll
    for (int i = 0; i < 8; i++) {
        size_t off = (size_t)(r0 + ty * 8 + i) * NND + c0 + tx * 8;
        float2 p0 = *(float2*)&acc[i][0], p1 = *(float2*)&acc[i][1];
        float2 p2 = *(float2*)&acc[i][2], p3 = *(float2*)&acc[i][3];
        float4 lo = make_float4(p0.x, p0.y, p1.x, p1.y);
        float4 hi = make_float4(p2.x, p2.y, p3.x, p3.y);
        *(float4*)(rec + off)          = lo;
        *(float4*)(rec + off + 4)      = hi;
        *(float4*)(rec + NN + off)     = lo;
        *(float4*)(rec + NN + off + 4) = hi;
    }

    if (bx != by) {
        // Mirror via 4 chunks of 32 columns, transposed through smem
        float* buf = sm;  // reuse, stride 132
#pragma unroll
        for (int c = 0; c < 4; c++) {
            __syncthreads();
            if ((tx >> 2) == c) {
                int cl0 = (tx & 3) * 8;
#pragma unroll
                for (int j = 0; j < 8; j++)
#pragma unroll
                    for (int i = 0; i < 8; i++)
                        buf[(cl0 + j) * 132 + ty * 8 + i] =
                            ((float*)&acc[i][j >> 1])[j & 1];
            }
            __syncthreads();
#pragma unroll
            for (int i2 = 0; i2 < 4; i2++) {
                int idx = tid + i2 * 256;
                int rowl = idx >> 5, c4 = idx & 31;
                float4 v = *(float4*)(buf + rowl * 132 + c4 * 4);
                size_t off = (size_t)(c0 + c * 32 + rowl) * NND + r0 + c4 * 4;
                *(float4*)(rec + off)      = v;
                *(float4*)(rec + NN + off) = v;
            }
        }
    }
}

// ---------------------------------------------------------------------------
extern "C" void kernel_launch(void* const* d_in, const int* in_sizes, int n_in,
                              void* d_out, int out_size) {
    const float* x  = (const float*)d_in[0];
    const float* W1 = (const float*)d_in[1];
    const float* W2 = (const float*)d_in[2];
    const float* ev = (const float*)d_in[3];
    const int*   er = (const int*)d_in[4];
    const int*   ec = (const int*)d_in[5];
    const int nE = in_sizes[3];

    float* out   = (float*)d_out;
    float* z_out = out;                     // [NND, D3]
    float* rec   = out + (size_t)NND * D3;  // [2, NND, NND]

    float *p_s1, *p_h, *p_s2, *p_eval;
    int *p_cnt, *p_off, *p_cur, *p_ecol;
    cudaGetSymbolAddress((void**)&p_s1,   g_s1);
    cudaGetSymbolAddress((void**)&p_h,    g_h);
    cudaGetSymbolAddress((void**)&p_s2,   g_s2);
    cudaGetSymbolAddress((void**)&p_cnt,  g_cnt);
    cudaGetSymbolAddress((void**)&p_off,  g_off);
    cudaGetSymbolAddress((void**)&p_cur,  g_cur);
    cudaGetSymbolAddress((void**)&p_ecol, g_ecol);
    cudaGetSymbolAddress((void**)&p_eval, g_eval);

    // Build CSR by destination row
    kzero_i<<<NND / 256, 256>>>(p_cnt, NND);
    count_edges<<<(nE + 255) / 256, 256>>>(er, p_cnt, nE);
    scan8192<<<1, 1024>>>(p_cnt, p_off);
    copy_off<<<NND / 256, 256>>>(p_off, p_cur, NND);
    scatter_edges<<<(nE + 255) / 256, 256>>>(er, ec, ev, p_cur, p_ecol, p_eval, nE);

    // Layer 1
    gemm128<<<dim3(D2 / 128, NND / 128), 256>>>(x, W1, p_s1, NND, D2, D1);
    spmm_gather<D2, true><<<NND, D2>>>(p_s1, p_off, p_ecol, p_eval, p_h);

    // Layer 2
    gemm128<<<dim3(D3 / 128, NND / 128), 256>>>(p_h, W2, p_s2, NND, D3, D2);
    spmm_gather<D3, true><<<NND, D3>>>(p_s2, p_off, p_ecol, p_eval, z_out);

    // Decoder: rec_views = stack([z @ z.T] * 2)
    zzsym<<<dim3(NND / 128, NND / 128), 256>>>(z_out, rec);
}